// round 4
// baseline (speedup 1.0000x reference)
#include <cuda_runtime.h>

// Problem constants (fixed by the reference)
#define B_  2
#define C_  4
#define K_  32
#define H_  96
#define W_  96
#define D_  64
#define NV  (D_*D_*D_)          // 262144 voxels per batch
#define HWK (H_*W_*K_)

// Transposed heatmaps: [b, c, h, w, k] with k contiguous (9.4 MB, L2-resident)
__device__ float g_hmT[B_ * C_ * HWK];

typedef unsigned long long ull;

__device__ __forceinline__ float frcp_approx(float x) {
    float r; asm("rcp.approx.f32 %0, %1;" : "=f"(r) : "f"(x)); return r;
}
__device__ __forceinline__ ull pack2(float a, float b) {
    ull r; asm("mov.b64 %0, {%1, %2};" : "=l"(r) : "f"(a), "f"(b)); return r;
}
__device__ __forceinline__ void unpack2(ull v, float& a, float& b) {
    asm("mov.b64 {%0, %1}, %2;" : "=f"(a), "=f"(b) : "l"(v));
}
// d = a*b + d on packed f32x2 (sm_103a FFMA2)
__device__ __forceinline__ void ffma2(ull& d, ull a, ull b) {
    asm("fma.rn.f32x2 %0, %1, %2, %0;" : "+l"(d) : "l"(a), "l"(b));
}

// ---------------------------------------------------------------------------
// Kernel 1: transpose (B,C,K,H,W) -> (B,C,H,W,K). 8 h-rows per block.
// ---------------------------------------------------------------------------
__global__ void vt_transpose_kernel(const float* __restrict__ hm) {
    __shared__ float tile[32][33];
    const int bc = blockIdx.z;
    const int w0 = blockIdx.x * 32;
    const int h0 = blockIdx.y * 8;

    #pragma unroll
    for (int hh = 0; hh < 8; hh++) {
        const int h = h0 + hh;
        tile[threadIdx.y][threadIdx.x] =
            hm[((bc * K_ + threadIdx.y) * H_ + h) * W_ + w0 + threadIdx.x];
        __syncthreads();
        g_hmT[((bc * H_ + h) * W_ + w0 + threadIdx.y) * K_ + threadIdx.x] =
            tile[threadIdx.x][threadIdx.y];
        __syncthreads();
    }
}

// ---------------------------------------------------------------------------
// Kernel 2: two-phase unprojection. Block = 256 threads = 32 voxels.
// Phase 1: threads 0..127 each compute setup for one (voxel, cam) pair.
// Phase 2: 8 threads/voxel branchless coalesced gather with packed FFMA2.
// ---------------------------------------------------------------------------
__global__ __launch_bounds__(256) void vt_unproject_kernel(
    const float* __restrict__ P,       // (B,C,3,4)
    const float* __restrict__ coords,  // (B,D,D,D,3)
    const float* __restrict__ conf,    // (B,C,K)
    float* __restrict__ out)           // (B,K,D,D,D)
{
    const int tid = threadIdx.x;
    const int b   = blockIdx.x >> 13;            // NV/32 = 8192 blocks/batch
    const int nb  = (blockIdx.x & 8191) * 32;    // base voxel within batch

    __shared__ float sP[C_ * 12];
    __shared__ float sCrd[32 * 3];
    __shared__ float sConf[C_][K_];
    __shared__ int   sIdx[128][4];     // premultiplied (*8) corner row indices
    __shared__ ull   sWp[128][4];      // packed (w,w) corner weights
    __shared__ float tile[32][33];

    if (tid < C_ * 12) sP[tid] = P[b * C_ * 12 + tid];
    if (tid < 96)      sCrd[tid] = coords[(b * NV + nb) * 3 + tid];
    if (tid >= 128) {
        const int t = tid - 128;
        const int c = t >> 5, k = t & 31;
        float s = 0.f;
        #pragma unroll
        for (int cc = 0; cc < C_; cc++) s += conf[(b * C_ + cc) * K_ + k];
        sConf[c][k] = conf[(b * C_ + c) * K_ + k] / s;
    }
    __syncthreads();

    // ---------------- Phase 1: setup (one (voxel, cam) pair per thread) ----
    if (tid < 128) {
        const int vox = tid >> 2, cam = tid & 3;
        const float x = sCrd[vox * 3 + 0];
        const float y = sCrd[vox * 3 + 1];
        const float z = sCrd[vox * 3 + 2];
        const float* p = &sP[cam * 12];

        const float pz = fmaf(p[8], x, fmaf(p[9], y, fmaf(p[10], z, p[11])));
        const bool zok = (pz > 0.f);

        const float s  = frcp_approx(pz) * (95.0f / 96.0f);
        const float un = fmaf(p[0], x, fmaf(p[1], y, fmaf(p[2], z, p[3])));
        const float vn = fmaf(p[4], x, fmaf(p[5], y, fmaf(p[6], z, p[7])));
        const float ix = un * s;
        const float iy = vn * s;

        const float x0f = floorf(ix), y0f = floorf(iy);
        const float x1f = x0f + 1.f,  y1f = y0f + 1.f;
        const float wx1 = ix - x0f,   wy1 = iy - y0f;
        const float wx0 = 1.f - wx1,  wy0 = 1.f - wy1;

        const bool bx0 = zok & (x0f >= 0.f) & (x0f <= 95.f);
        const bool bx1 = zok & (x1f >= 0.f) & (x1f <= 95.f);
        const bool by0 = (y0f >= 0.f) & (y0f <= 95.f);
        const bool by1 = (y1f >= 0.f) & (y1f <= 95.f);

        int  id[4];
        ull  wp[4];
        #define VT_SETUP(J, BX, BY, XF, YF, WX, WY)                           \
            {                                                                 \
                const bool v = (BX) & (BY);                                   \
                const int  raw = (int)fmaf((YF), 96.f, (XF)) * 8;             \
                const float wc = (WX) * (WY);                                 \
                id[J] = v ? raw : 0;                                          \
                const float wv = v ? wc : 0.f;                                \
                wp[J] = pack2(wv, wv);                                        \
            }
        VT_SETUP(0, bx0, by0, x0f, y0f, wx0, wy0)
        VT_SETUP(1, bx1, by0, x1f, y0f, wx1, wy0)
        VT_SETUP(2, bx0, by1, x0f, y1f, wx0, wy1)
        VT_SETUP(3, bx1, by1, x1f, y1f, wx1, wy1)
        #undef VT_SETUP

        *(int4*)&sIdx[tid][0] = make_int4(id[0], id[1], id[2], id[3]);
        sWp[tid][0] = wp[0];
        sWp[tid][1] = wp[1];
        sWp[tid][2] = wp[2];
        sWp[tid][3] = wp[3];
    }
    __syncthreads();

    // ---------------- Phase 2: branchless gather (8 threads per voxel) -----
    const int g    = tid & 7;          // channel quad
    const int vloc = tid >> 3;         // voxel within block

    // packed confidences for this thread's 4 channels, per camera
    ull cpk[C_][2];
    #pragma unroll
    for (int c = 0; c < C_; c++) {
        const float2* cf = (const float2*)&sConf[c][4 * g];
        const float2 c0 = cf[0], c1 = cf[1];
        cpk[c][0] = pack2(c0.x, c0.y);
        cpk[c][1] = pack2(c1.x, c1.y);
    }

    ull acc0 = 0ull, acc1 = 0ull;
    const float4* hb4 = (const float4*)&g_hmT[b * C_ * HWK] + g;

    #pragma unroll
    for (int c = 0; c < C_; c++) {
        const float4* cb = hb4 + c * (HWK / 4);
        const int pr = vloc * 4 + c;
        const int4 id = *(const int4*)&sIdx[pr][0];
        const ull w0 = sWp[pr][0], w1 = sWp[pr][1];
        const ull w2 = sWp[pr][2], w3 = sWp[pr][3];

        ull cam0 = 0ull, cam1 = 0ull;
        float4 v;
        v = cb[id.x]; ffma2(cam0, w0, pack2(v.x, v.y)); ffma2(cam1, w0, pack2(v.z, v.w));
        v = cb[id.y]; ffma2(cam0, w1, pack2(v.x, v.y)); ffma2(cam1, w1, pack2(v.z, v.w));
        v = cb[id.z]; ffma2(cam0, w2, pack2(v.x, v.y)); ffma2(cam1, w2, pack2(v.z, v.w));
        v = cb[id.w]; ffma2(cam0, w3, pack2(v.x, v.y)); ffma2(cam1, w3, pack2(v.z, v.w));

        ffma2(acc0, cam0, cpk[c][0]);
        ffma2(acc1, cam1, cpk[c][1]);
    }

    // stage into smem for coalesced writeout
    float a0, a1, a2, a3;
    unpack2(acc0, a0, a1);
    unpack2(acc1, a2, a3);
    tile[vloc][4 * g + 0] = a0;
    tile[vloc][4 * g + 1] = a1;
    tile[vloc][4 * g + 2] = a2;
    tile[vloc][4 * g + 3] = a3;
    __syncthreads();

    const int i  = tid & 31;   // voxel within block
    const int kb = tid >> 5;   // 0..7
    #pragma unroll
    for (int r = 0; r < 4; r++) {
        const int k = r * 8 + kb;
        out[(b * K_ + k) * NV + nb + i] = tile[i][k];
    }
}

// ---------------------------------------------------------------------------
// Launch
// ---------------------------------------------------------------------------
extern "C" void kernel_launch(void* const* d_in, const int* in_sizes, int n_in,
                              void* d_out, int out_size) {
    const float* heatmaps = (const float*)d_in[0];  // (B,C,K,H,W)
    const float* P        = (const float*)d_in[1];  // (B,C,3,4)
    const float* coords   = (const float*)d_in[2];  // (B,D,D,D,3)
    const float* conf     = (const float*)d_in[3];  // (B,C,K)
    float* out            = (float*)d_out;          // (B,K,D,D,D)

    dim3 tgrid(W_ / 32, H_ / 8, B_ * C_);
    dim3 tblk(32, 32);
    vt_transpose_kernel<<<tgrid, tblk>>>(heatmaps);

    const int nblocks = (B_ * NV) / 32;   // 32 voxels per block
    vt_unproject_kernel<<<nblocks, 256>>>(P, coords, conf, out);
}

// round 5
// speedup vs baseline: 1.3245x; 1.3245x over previous
#include <cuda_runtime.h>

// Problem constants (fixed by the reference)
#define B_  2
#define C_  4
#define K_  32
#define H_  96
#define W_  96
#define D_  64
#define NV  (D_*D_*D_)          // 262144 voxels per batch
#define HWK (H_*W_*K_)

// Transposed, confidence-scaled heatmaps: [b,c,h,w,k], k contiguous (9.4 MB)
__device__ float g_hmT[B_ * C_ * HWK];

__device__ __forceinline__ float frcp_approx(float x) {
    float r; asm("rcp.approx.f32 %0, %1;" : "=f"(r) : "f"(x)); return r;
}

// ---------------------------------------------------------------------------
// Kernel 1: transpose (B,C,K,H,W) -> (B,C,H,W,K), folding in normalized conf.
// grid (W/32, H/8, B*C), block (32,32)
// ---------------------------------------------------------------------------
__global__ void vt_transpose_kernel(const float* __restrict__ hm,
                                    const float* __restrict__ conf) {
    __shared__ float tile[32][33];
    __shared__ float sCn[32];
    const int bc = blockIdx.z;            // b*C + c
    const int b  = bc >> 2;
    const int w0 = blockIdx.x * 32;
    const int h0 = blockIdx.y * 8;

    if (threadIdx.y == 0) {
        const int k = threadIdx.x;
        float s = 0.f;
        #pragma unroll
        for (int cc = 0; cc < C_; cc++) s += conf[(b * C_ + cc) * K_ + k];
        sCn[k] = conf[bc * K_ + k] / s;
    }
    __syncthreads();

    const float cn = sCn[threadIdx.y];    // k = threadIdx.y on the read side
    #pragma unroll
    for (int hh = 0; hh < 8; hh++) {
        const int h = h0 + hh;
        tile[threadIdx.y][threadIdx.x] =
            hm[((bc * K_ + threadIdx.y) * H_ + h) * W_ + w0 + threadIdx.x] * cn;
        __syncthreads();
        g_hmT[((bc * H_ + h) * W_ + w0 + threadIdx.y) * K_ + threadIdx.x] =
            tile[threadIdx.x][threadIdx.y];
        __syncthreads();
    }
}

// ---------------------------------------------------------------------------
// Kernel 2: two-phase unprojection. Block = 256 threads = 32 voxels.
// Phase 1: threads 0..127 compute setup for one (voxel, cam) pair each.
// Phase 2: 8 threads/voxel, predicated coalesced gathers (skip zero weights),
//          accumulating conf-scaled heatmap values directly.
// ---------------------------------------------------------------------------
__global__ __launch_bounds__(256) void vt_unproject_kernel(
    const float* __restrict__ P,       // (B,C,3,4)
    const float* __restrict__ coords,  // (B,D,D,D,3)
    float* __restrict__ out)           // (B,K,D,D,D)
{
    const int tid = threadIdx.x;
    const int b   = blockIdx.x >> 13;            // NV/32 = 8192 blocks/batch
    const int nb  = (blockIdx.x & 8191) * 32;    // base voxel within batch

    __shared__ float  sP[C_ * 12];
    __shared__ float  sCrd[32 * 3];
    __shared__ int4   sIdx[128];       // premultiplied (*8) corner row indices
    __shared__ float4 sW[128];         // corner weights (0 if invalid)
    __shared__ float  tile[32][33];

    if (tid < C_ * 12) sP[tid] = P[b * C_ * 12 + tid];
    else if (tid >= 128 && tid < 128 + 96)
        sCrd[tid - 128] = coords[(b * NV + nb) * 3 + (tid - 128)];
    __syncthreads();

    // ---------------- Phase 1: setup (one (voxel, cam) pair per thread) ----
    if (tid < 128) {
        const int vox = tid >> 2, cam = tid & 3;
        const float x = sCrd[vox * 3 + 0];
        const float y = sCrd[vox * 3 + 1];
        const float z = sCrd[vox * 3 + 2];
        const float* p = &sP[cam * 12];

        const float pz = fmaf(p[8], x, fmaf(p[9], y, fmaf(p[10], z, p[11])));
        const bool zok = (pz > 0.f);

        const float s  = frcp_approx(pz) * (95.0f / 96.0f);
        const float un = fmaf(p[0], x, fmaf(p[1], y, fmaf(p[2], z, p[3])));
        const float vn = fmaf(p[4], x, fmaf(p[5], y, fmaf(p[6], z, p[7])));
        const float ix = un * s;
        const float iy = vn * s;

        const float x0f = floorf(ix), y0f = floorf(iy);
        const float x1f = x0f + 1.f,  y1f = y0f + 1.f;
        const float wx1 = ix - x0f,   wy1 = iy - y0f;
        const float wx0 = 1.f - wx1,  wy0 = 1.f - wy1;

        const bool bx0 = zok & (x0f >= 0.f) & (x0f <= 95.f);
        const bool bx1 = zok & (x1f >= 0.f) & (x1f <= 95.f);
        const bool by0 = (y0f >= 0.f) & (y0f <= 95.f);
        const bool by1 = (y1f >= 0.f) & (y1f <= 95.f);

        int   id[4];
        float wv[4];
        #define VT_SETUP(J, BX, BY, XF, YF, WX, WY)                           \
            {                                                                 \
                const bool v = (BX) & (BY);                                   \
                const int raw = (int)fmaf((YF), 96.f, (XF)) * 8;              \
                id[J] = v ? raw : 0;                                          \
                wv[J] = v ? (WX) * (WY) : 0.f;                                \
            }
        VT_SETUP(0, bx0, by0, x0f, y0f, wx0, wy0)
        VT_SETUP(1, bx1, by0, x1f, y0f, wx1, wy0)
        VT_SETUP(2, bx0, by1, x0f, y1f, wx0, wy1)
        VT_SETUP(3, bx1, by1, x1f, y1f, wx1, wy1)
        #undef VT_SETUP

        sIdx[tid] = make_int4(id[0], id[1], id[2], id[3]);
        sW[tid]   = make_float4(wv[0], wv[1], wv[2], wv[3]);
    }
    __syncthreads();

    // ---------------- Phase 2: predicated gather (8 threads per voxel) -----
    const int g    = tid & 7;          // channel quad
    const int vloc = tid >> 3;         // voxel within block

    float4 acc = make_float4(0.f, 0.f, 0.f, 0.f);
    const float4* hb4 = (const float4*)&g_hmT[b * C_ * HWK] + g;

    #pragma unroll
    for (int c = 0; c < C_; c++) {
        const float4* cb = hb4 + c * (HWK / 4);
        const int pr = vloc * 4 + c;
        const int4   id = sIdx[pr];
        const float4 w  = sW[pr];

        #define VT_CORNER(II, WW)                                             \
            if ((WW) != 0.f) {                                                \
                const float4 v = cb[II];                                      \
                acc.x = fmaf((WW), v.x, acc.x);                               \
                acc.y = fmaf((WW), v.y, acc.y);                               \
                acc.z = fmaf((WW), v.z, acc.z);                               \
                acc.w = fmaf((WW), v.w, acc.w);                               \
            }
        VT_CORNER(id.x, w.x)
        VT_CORNER(id.y, w.y)
        VT_CORNER(id.z, w.z)
        VT_CORNER(id.w, w.w)
        #undef VT_CORNER
    }

    // stage into smem for coalesced writeout
    tile[vloc][4 * g + 0] = acc.x;
    tile[vloc][4 * g + 1] = acc.y;
    tile[vloc][4 * g + 2] = acc.z;
    tile[vloc][4 * g + 3] = acc.w;
    __syncthreads();

    const int i  = tid & 31;   // voxel within block
    const int kb = tid >> 5;   // 0..7
    #pragma unroll
    for (int r = 0; r < 4; r++) {
        const int k = r * 8 + kb;
        out[(b * K_ + k) * NV + nb + i] = tile[i][k];
    }
}

// ---------------------------------------------------------------------------
// Launch
// ---------------------------------------------------------------------------
extern "C" void kernel_launch(void* const* d_in, const int* in_sizes, int n_in,
                              void* d_out, int out_size) {
    const float* heatmaps = (const float*)d_in[0];  // (B,C,K,H,W)
    const float* P        = (const float*)d_in[1];  // (B,C,3,4)
    const float* coords   = (const float*)d_in[2];  // (B,D,D,D,3)
    const float* conf     = (const float*)d_in[3];  // (B,C,K)
    float* out            = (float*)d_out;          // (B,K,D,D,D)

    dim3 tgrid(W_ / 32, H_ / 8, B_ * C_);
    dim3 tblk(32, 32);
    vt_transpose_kernel<<<tgrid, tblk>>>(heatmaps, conf);

    const int nblocks = (B_ * NV) / 32;   // 32 voxels per block
    vt_unproject_kernel<<<nblocks, 256>>>(P, coords, out);
}

// round 6
// speedup vs baseline: 1.6312x; 1.2315x over previous
#include <cuda_runtime.h>
#include <cuda_fp16.h>

// Problem constants (fixed by the reference)
#define B_  2
#define C_  4
#define K_  32
#define H_  96
#define W_  96
#define D_  64
#define NV  (D_*D_*D_)          // 262144 voxels per batch
#define HWK (H_*W_*K_)

// Transposed, confidence-scaled heatmaps in fp16: [b,c,h,w,k] (4.7 MB)
__device__ __half g_hmT[B_ * C_ * HWK];

__device__ __forceinline__ float frcp_approx(float x) {
    float r; asm("rcp.approx.f32 %0, %1;" : "=f"(r) : "f"(x)); return r;
}

// ---------------------------------------------------------------------------
// Kernel 1: transpose (B,C,K,H,W) -> fp16 (B,C,H,W,K), folding normalized conf.
// grid (W/32, H/8, B*C), block (32,32)
// ---------------------------------------------------------------------------
__global__ void vt_transpose_kernel(const float* __restrict__ hm,
                                    const float* __restrict__ conf) {
    __shared__ float tile[32][33];
    __shared__ float sCn[32];
    const int bc = blockIdx.z;            // b*C + c
    const int b  = bc >> 2;
    const int w0 = blockIdx.x * 32;
    const int h0 = blockIdx.y * 8;

    if (threadIdx.y == 0) {
        const int k = threadIdx.x;
        float s = 0.f;
        #pragma unroll
        for (int cc = 0; cc < C_; cc++) s += conf[(b * C_ + cc) * K_ + k];
        sCn[k] = conf[bc * K_ + k] / s;
    }
    __syncthreads();

    const float cn = sCn[threadIdx.y];    // k = threadIdx.y on the read side
    #pragma unroll
    for (int hh = 0; hh < 8; hh++) {
        const int h = h0 + hh;
        tile[threadIdx.y][threadIdx.x] =
            hm[((bc * K_ + threadIdx.y) * H_ + h) * W_ + w0 + threadIdx.x] * cn;
        __syncthreads();
        g_hmT[((bc * H_ + h) * W_ + w0 + threadIdx.y) * K_ + threadIdx.x] =
            __float2half_rn(tile[threadIdx.x][threadIdx.y]);
        __syncthreads();
    }
}

// ---------------------------------------------------------------------------
// Kernel 2: two-phase unprojection. Block = 256 threads = 32 voxels.
// Phase 1: threads 0..127 compute setup for one (voxel, cam) pair each.
// Phase 2: 8 threads/voxel, predicated coalesced fp16 gathers (uint2 = 4 ch),
//          converted to fp32 and accumulated.
// ---------------------------------------------------------------------------
__global__ __launch_bounds__(256) void vt_unproject_kernel(
    const float* __restrict__ P,       // (B,C,3,4)
    const float* __restrict__ coords,  // (B,D,D,D,3)
    float* __restrict__ out)           // (B,K,D,D,D)
{
    const int tid = threadIdx.x;
    const int b   = blockIdx.x >> 13;            // NV/32 = 8192 blocks/batch
    const int nb  = (blockIdx.x & 8191) * 32;    // base voxel within batch

    __shared__ float  sP[C_ * 12];
    __shared__ float  sCrd[32 * 3];
    __shared__ int4   sIdx[128];       // premultiplied (*8) corner row indices
    __shared__ float4 sW[128];         // corner weights (0 if invalid)
    __shared__ float  tile[32][33];

    if (tid < C_ * 12) sP[tid] = P[b * C_ * 12 + tid];
    else if (tid >= 128 && tid < 128 + 96)
        sCrd[tid - 128] = coords[(b * NV + nb) * 3 + (tid - 128)];
    __syncthreads();

    // ---------------- Phase 1: setup (one (voxel, cam) pair per thread) ----
    if (tid < 128) {
        const int vox = tid >> 2, cam = tid & 3;
        const float x = sCrd[vox * 3 + 0];
        const float y = sCrd[vox * 3 + 1];
        const float z = sCrd[vox * 3 + 2];
        const float* p = &sP[cam * 12];

        const float pz = fmaf(p[8], x, fmaf(p[9], y, fmaf(p[10], z, p[11])));
        const bool zok = (pz > 0.f);

        const float s  = frcp_approx(pz) * (95.0f / 96.0f);
        const float un = fmaf(p[0], x, fmaf(p[1], y, fmaf(p[2], z, p[3])));
        const float vn = fmaf(p[4], x, fmaf(p[5], y, fmaf(p[6], z, p[7])));
        const float ix = un * s;
        const float iy = vn * s;

        const float x0f = floorf(ix), y0f = floorf(iy);
        const float x1f = x0f + 1.f,  y1f = y0f + 1.f;
        const float wx1 = ix - x0f,   wy1 = iy - y0f;
        const float wx0 = 1.f - wx1,  wy0 = 1.f - wy1;

        const bool bx0 = zok & (x0f >= 0.f) & (x0f <= 95.f);
        const bool bx1 = zok & (x1f >= 0.f) & (x1f <= 95.f);
        const bool by0 = (y0f >= 0.f) & (y0f <= 95.f);
        const bool by1 = (y1f >= 0.f) & (y1f <= 95.f);

        int   id[4];
        float wv[4];
        #define VT_SETUP(J, BX, BY, XF, YF, WX, WY)                           \
            {                                                                 \
                const bool v = (BX) & (BY);                                   \
                const int raw = (int)fmaf((YF), 96.f, (XF)) * 8;              \
                id[J] = v ? raw : 0;                                          \
                wv[J] = v ? (WX) * (WY) : 0.f;                                \
            }
        VT_SETUP(0, bx0, by0, x0f, y0f, wx0, wy0)
        VT_SETUP(1, bx1, by0, x1f, y0f, wx1, wy0)
        VT_SETUP(2, bx0, by1, x0f, y1f, wx0, wy1)
        VT_SETUP(3, bx1, by1, x1f, y1f, wx1, wy1)
        #undef VT_SETUP

        sIdx[tid] = make_int4(id[0], id[1], id[2], id[3]);
        sW[tid]   = make_float4(wv[0], wv[1], wv[2], wv[3]);
    }
    __syncthreads();

    // ---------------- Phase 2: predicated fp16 gather (8 threads/voxel) ----
    const int g    = tid & 7;          // channel quad
    const int vloc = tid >> 3;         // voxel within block

    float4 acc = make_float4(0.f, 0.f, 0.f, 0.f);
    // rows are 32 halves = 8 uint2; thread g takes uint2 #g
    const uint2* hb = (const uint2*)g_hmT + b * C_ * (HWK / 4) + g;

    #pragma unroll
    for (int c = 0; c < C_; c++) {
        const uint2* cb = hb + c * (HWK / 4);
        const int pr = vloc * 4 + c;
        const int4   id = sIdx[pr];
        const float4 w  = sW[pr];

        #define VT_CORNER(II, WW)                                             \
            if ((WW) != 0.f) {                                                \
                const uint2 v = cb[II];                                       \
                const float2 f0 = __half22float2(*(const __half2*)&v.x);      \
                const float2 f1 = __half22float2(*(const __half2*)&v.y);      \
                acc.x = fmaf((WW), f0.x, acc.x);                              \
                acc.y = fmaf((WW), f0.y, acc.y);                              \
                acc.z = fmaf((WW), f1.x, acc.z);                              \
                acc.w = fmaf((WW), f1.y, acc.w);                              \
            }
        VT_CORNER(id.x, w.x)
        VT_CORNER(id.y, w.y)
        VT_CORNER(id.z, w.z)
        VT_CORNER(id.w, w.w)
        #undef VT_CORNER
    }

    // stage into smem for coalesced writeout
    tile[vloc][4 * g + 0] = acc.x;
    tile[vloc][4 * g + 1] = acc.y;
    tile[vloc][4 * g + 2] = acc.z;
    tile[vloc][4 * g + 3] = acc.w;
    __syncthreads();

    const int i  = tid & 31;   // voxel within block
    const int kb = tid >> 5;   // 0..7
    #pragma unroll
    for (int r = 0; r < 4; r++) {
        const int k = r * 8 + kb;
        out[(b * K_ + k) * NV + nb + i] = tile[i][k];
    }
}

// ---------------------------------------------------------------------------
// Launch
// ---------------------------------------------------------------------------
extern "C" void kernel_launch(void* const* d_in, const int* in_sizes, int n_in,
                              void* d_out, int out_size) {
    const float* heatmaps = (const float*)d_in[0];  // (B,C,K,H,W)
    const float* P        = (const float*)d_in[1];  // (B,C,3,4)
    const float* coords   = (const float*)d_in[2];  // (B,D,D,D,3)
    const float* conf     = (const float*)d_in[3];  // (B,C,K)
    float* out            = (float*)d_out;          // (B,K,D,D,D)

    dim3 tgrid(W_ / 32, H_ / 8, B_ * C_);
    dim3 tblk(32, 32);
    vt_transpose_kernel<<<tgrid, tblk>>>(heatmaps, conf);

    const int nblocks = (B_ * NV) / 32;   // 32 voxels per block
    vt_unproject_kernel<<<nblocks, 256>>>(P, coords, out);
}

// round 7
// speedup vs baseline: 1.7079x; 1.0471x over previous
#include <cuda_runtime.h>
#include <cuda_fp16.h>

// Problem constants (fixed by the reference)
#define B_  2
#define C_  4
#define K_  32
#define H_  96
#define W_  96
#define D_  64
#define NV  (D_*D_*D_)          // 262144 voxels per batch
#define HWK (H_*W_*K_)

// Transposed, confidence-scaled heatmaps in fp16: [b,c,h,w,k] (4.7 MB)
__device__ __half g_hmT[B_ * C_ * HWK];

__device__ __forceinline__ float frcp_approx(float x) {
    float r; asm("rcp.approx.f32 %0, %1;" : "=f"(r) : "f"(x)); return r;
}
__device__ __forceinline__ __half2 u2h(unsigned v) {
    __half2 h; *(unsigned*)&h = v; return h;
}

// ---------------------------------------------------------------------------
// Kernel 1: transpose (B,C,K,H,W) -> fp16 (B,C,H,W,K), folding normalized conf.
// grid (W/32, H/8, B*C), block (32,32)
// ---------------------------------------------------------------------------
__global__ void vt_transpose_kernel(const float* __restrict__ hm,
                                    const float* __restrict__ conf) {
    __shared__ float tile[32][33];
    __shared__ float sCn[32];
    const int bc = blockIdx.z;            // b*C + c
    const int b  = bc >> 2;
    const int w0 = blockIdx.x * 32;
    const int h0 = blockIdx.y * 8;

    if (threadIdx.y == 0) {
        const int k = threadIdx.x;
        float s = 0.f;
        #pragma unroll
        for (int cc = 0; cc < C_; cc++) s += conf[(b * C_ + cc) * K_ + k];
        sCn[k] = conf[bc * K_ + k] / s;
    }
    __syncthreads();

    const float cn = sCn[threadIdx.y];    // k = threadIdx.y on the read side
    #pragma unroll
    for (int hh = 0; hh < 8; hh++) {
        const int h = h0 + hh;
        tile[threadIdx.y][threadIdx.x] =
            hm[((bc * K_ + threadIdx.y) * H_ + h) * W_ + w0 + threadIdx.x] * cn;
        __syncthreads();
        g_hmT[((bc * H_ + h) * W_ + w0 + threadIdx.y) * K_ + threadIdx.x] =
            __float2half_rn(tile[threadIdx.x][threadIdx.y]);
        __syncthreads();
    }
}

// ---------------------------------------------------------------------------
// Kernel 2: two-phase unprojection. Block = 256 threads = 32 voxels.
// Phase 1: threads 0..127 compute setup for one (voxel, cam) pair each;
//          corner weights stored pre-packed as half2(w,w) bits.
// Phase 2: 8 threads/voxel: predicated coalesced fp16 gathers, bilinear
//          combine in HFMA2, one fp32 convert+add per camera.
// ---------------------------------------------------------------------------
__global__ __launch_bounds__(256) void vt_unproject_kernel(
    const float* __restrict__ P,       // (B,C,3,4)
    const float* __restrict__ coords,  // (B,D,D,D,3)
    float* __restrict__ out)           // (B,K,D,D,D)
{
    const int tid = threadIdx.x;
    const int b   = blockIdx.x >> 13;            // NV/32 = 8192 blocks/batch
    const int nb  = (blockIdx.x & 8191) * 32;    // base voxel within batch

    __shared__ float  sP[C_ * 12];
    __shared__ float  sCrd[32 * 3];
    __shared__ int4   sIdx[128];       // premultiplied (*8) corner row indices
    __shared__ uint4  sWh[128];        // packed half2(w,w) corner weights
    __shared__ float  tile[32][33];

    if (tid < C_ * 12) sP[tid] = P[b * C_ * 12 + tid];
    else if (tid >= 128 && tid < 128 + 96)
        sCrd[tid - 128] = coords[(b * NV + nb) * 3 + (tid - 128)];
    __syncthreads();

    // ---------------- Phase 1: setup (one (voxel, cam) pair per thread) ----
    if (tid < 128) {
        const int vox = tid >> 2, cam = tid & 3;
        const float x = sCrd[vox * 3 + 0];
        const float y = sCrd[vox * 3 + 1];
        const float z = sCrd[vox * 3 + 2];
        const float* p = &sP[cam * 12];

        const float pz = fmaf(p[8], x, fmaf(p[9], y, fmaf(p[10], z, p[11])));
        const bool zok = (pz > 0.f);

        const float s  = frcp_approx(pz) * (95.0f / 96.0f);
        const float un = fmaf(p[0], x, fmaf(p[1], y, fmaf(p[2], z, p[3])));
        const float vn = fmaf(p[4], x, fmaf(p[5], y, fmaf(p[6], z, p[7])));
        const float ix = un * s;
        const float iy = vn * s;

        const float x0f = floorf(ix), y0f = floorf(iy);
        const float x1f = x0f + 1.f,  y1f = y0f + 1.f;
        const float wx1 = ix - x0f,   wy1 = iy - y0f;
        const float wx0 = 1.f - wx1,  wy0 = 1.f - wy1;

        const bool bx0 = zok & (x0f >= 0.f) & (x0f <= 95.f);
        const bool bx1 = zok & (x1f >= 0.f) & (x1f <= 95.f);
        const bool by0 = (y0f >= 0.f) & (y0f <= 95.f);
        const bool by1 = (y1f >= 0.f) & (y1f <= 95.f);

        int      id[4];
        unsigned wh[4];
        #define VT_SETUP(J, BX, BY, XF, YF, WX, WY)                           \
            {                                                                 \
                const bool v = (BX) & (BY);                                   \
                const int raw = (int)fmaf((YF), 96.f, (XF)) * 8;              \
                id[J] = v ? raw : 0;                                          \
                const float wc = v ? (WX) * (WY) : 0.f;                       \
                const __half2 h = __float2half2_rn(wc);                       \
                wh[J] = *(const unsigned*)&h;                                 \
            }
        VT_SETUP(0, bx0, by0, x0f, y0f, wx0, wy0)
        VT_SETUP(1, bx1, by0, x1f, y0f, wx1, wy0)
        VT_SETUP(2, bx0, by1, x0f, y1f, wx0, wy1)
        VT_SETUP(3, bx1, by1, x1f, y1f, wx1, wy1)
        #undef VT_SETUP

        sIdx[tid] = make_int4(id[0], id[1], id[2], id[3]);
        sWh[tid]  = make_uint4(wh[0], wh[1], wh[2], wh[3]);
    }
    __syncthreads();

    // ---------------- Phase 2: fp16 gather + HFMA2 combine ------------------
    const int g    = tid & 7;          // channel quad
    const int vloc = tid >> 3;         // voxel within block

    float4 acc = make_float4(0.f, 0.f, 0.f, 0.f);
    // rows are 32 halves = 8 uint2; thread g takes uint2 #g
    const uint2* hb = (const uint2*)g_hmT + b * C_ * (HWK / 4) + g;

    #pragma unroll
    for (int c = 0; c < C_; c++) {
        const uint2* cb = hb + c * (HWK / 4);
        const int pr = vloc * 4 + c;
        const int4  id = sIdx[pr];
        const uint4 wh = sWh[pr];

        __half2 cam0 = u2h(0u), cam1 = u2h(0u);

        #define VT_CORNER(II, WW)                                             \
            if (WW) {                                                         \
                const uint2 v = cb[II];                                       \
                cam0 = __hfma2(u2h(WW), u2h(v.x), cam0);                      \
                cam1 = __hfma2(u2h(WW), u2h(v.y), cam1);                      \
            }
        VT_CORNER(id.x, wh.x)
        VT_CORNER(id.y, wh.y)
        VT_CORNER(id.z, wh.z)
        VT_CORNER(id.w, wh.w)
        #undef VT_CORNER

        const float2 f0 = __half22float2(cam0);
        const float2 f1 = __half22float2(cam1);
        acc.x += f0.x;
        acc.y += f0.y;
        acc.z += f1.x;
        acc.w += f1.y;
    }

    // stage into smem for coalesced writeout
    tile[vloc][4 * g + 0] = acc.x;
    tile[vloc][4 * g + 1] = acc.y;
    tile[vloc][4 * g + 2] = acc.z;
    tile[vloc][4 * g + 3] = acc.w;
    __syncthreads();

    const int i  = tid & 31;   // voxel within block
    const int kb = tid >> 5;   // 0..7
    #pragma unroll
    for (int r = 0; r < 4; r++) {
        const int k = r * 8 + kb;
        out[(b * K_ + k) * NV + nb + i] = tile[i][k];
    }
}

// ---------------------------------------------------------------------------
// Launch
// ---------------------------------------------------------------------------
extern "C" void kernel_launch(void* const* d_in, const int* in_sizes, int n_in,
                              void* d_out, int out_size) {
    const float* heatmaps = (const float*)d_in[0];  // (B,C,K,H,W)
    const float* P        = (const float*)d_in[1];  // (B,C,3,4)
    const float* coords   = (const float*)d_in[2];  // (B,D,D,D,3)
    const float* conf     = (const float*)d_in[3];  // (B,C,K)
    float* out            = (float*)d_out;          // (B,K,D,D,D)

    dim3 tgrid(W_ / 32, H_ / 8, B_ * C_);
    dim3 tblk(32, 32);
    vt_transpose_kernel<<<tgrid, tblk>>>(heatmaps, conf);

    const int nblocks = (B_ * NV) / 32;   // 32 voxels per block
    vt_unproject_kernel<<<nblocks, 256>>>(P, coords, out);
}

// round 8
// speedup vs baseline: 1.8499x; 1.0831x over previous
#include <cuda_runtime.h>
#include <cuda_fp16.h>

// Problem constants (fixed by the reference)
#define B_  2
#define C_  4
#define K_  32
#define H_  96
#define W_  96
#define D_  64
#define NV  (D_*D_*D_)          // 262144 voxels per batch
#define HWK (H_*W_*K_)

// Transposed, confidence-scaled heatmaps in fp16: [b,c,h,w,k] (4.7 MB)
__device__ __half g_hmT[B_ * C_ * HWK];

__device__ __forceinline__ float frcp_approx(float x) {
    float r; asm("rcp.approx.f32 %0, %1;" : "=f"(r) : "f"(x)); return r;
}
__device__ __forceinline__ __half2 u2h(unsigned v) {
    __half2 h; *(unsigned*)&h = v; return h;
}

// ---------------------------------------------------------------------------
// Kernel 1: transpose (B,C,K,H,W) -> fp16 (B,C,H,W,K), folding normalized conf.
// grid (W/32, H/8, B*C), block (32,32). Writes half2 (full 128B/warp stores).
// ---------------------------------------------------------------------------
__global__ void vt_transpose_kernel(const float* __restrict__ hm,
                                    const float* __restrict__ conf) {
    __shared__ float tile[2][32][33];
    __shared__ float sCn[32];
    const int bc = blockIdx.z;            // b*C + c
    const int b  = bc >> 2;
    const int w0 = blockIdx.x * 32;
    const int h0 = blockIdx.y * 8;
    const int tx = threadIdx.x, ty = threadIdx.y;
    const int tid = ty * 32 + tx;

    if (ty == 0) {
        const int k = tx;
        float s = 0.f;
        #pragma unroll
        for (int cc = 0; cc < C_; cc++) s += conf[(b * C_ + cc) * K_ + k];
        sCn[k] = conf[bc * K_ + k] / s;
    }
    __syncthreads();

    const float cn = sCn[ty];             // k = ty on the read side
    // write-phase decode: r = h-row pair member, w_local, k2 (half2 index)
    const int wr = tid >> 9;              // 0/1
    const int wi = tid & 511;
    const int w_local = wi >> 4;          // 0..31
    const int k2 = wi & 15;               // 0..15 (half2 per row)

    __half2* outT = (__half2*)g_hmT;

    #pragma unroll
    for (int hh = 0; hh < 8; hh += 2) {
        #pragma unroll
        for (int r = 0; r < 2; r++) {
            const int h = h0 + hh + r;
            tile[r][ty][tx] =
                hm[((bc * K_ + ty) * H_ + h) * W_ + w0 + tx] * cn;
        }
        __syncthreads();
        {
            const int h = h0 + hh + wr;
            const float a0 = tile[wr][2 * k2 + 0][w_local];
            const float a1 = tile[wr][2 * k2 + 1][w_local];
            outT[(((bc * H_ + h) * W_ + w0 + w_local) * K_) / 2 + k2] =
                __floats2half2_rn(a0, a1);
        }
        __syncthreads();
    }
}

// ---------------------------------------------------------------------------
// Kernel 2: two-phase unprojection. Block = 128 threads = 32 voxels.
// Phase 1: every thread computes setup for one (voxel, cam) pair; each corner
//          packed into one uint: low16 = row index*4 (uint4 units),
//          high16 = fp16 weight bits (0 if invalid).
// Phase 2: 4 threads/voxel (8 channels each, uint4 = 8 fp16). Per camera:
//          one LDS.128, whole-camera skip, 4 predicated LDG.128 + HFMA2,
//          one fp32 convert+add.
// ---------------------------------------------------------------------------
__global__ __launch_bounds__(128, 12) void vt_unproject_kernel(
    const float* __restrict__ P,       // (B,C,3,4)
    const float* __restrict__ coords,  // (B,D,D,D,3)
    float* __restrict__ out)           // (B,K,D,D,D)
{
    const int tid = threadIdx.x;
    const int b   = blockIdx.x >> 13;            // NV/32 = 8192 blocks/batch
    const int nb  = (blockIdx.x & 8191) * 32;    // base voxel within batch

    __shared__ float sP[C_ * 12];
    __shared__ float sCrd[32 * 3];
    __shared__ uint4 sPack[128];       // packed (idx*4 | wh<<16) per corner
    __shared__ float tile[32][33];

    if (tid < C_ * 12) sP[tid] = P[b * C_ * 12 + tid];
    if (tid < 96)      sCrd[tid] = coords[(b * NV + nb) * 3 + tid];
    __syncthreads();

    // ---------------- Phase 1: setup (one (voxel, cam) pair per thread) ----
    {
        const int vox = tid >> 2, cam = tid & 3;
        const float x = sCrd[vox * 3 + 0];
        const float y = sCrd[vox * 3 + 1];
        const float z = sCrd[vox * 3 + 2];
        const float* p = &sP[cam * 12];

        const float pz = fmaf(p[8], x, fmaf(p[9], y, fmaf(p[10], z, p[11])));
        const bool zok = (pz > 0.f);

        const float s  = frcp_approx(pz) * (95.0f / 96.0f);
        const float un = fmaf(p[0], x, fmaf(p[1], y, fmaf(p[2], z, p[3])));
        const float vn = fmaf(p[4], x, fmaf(p[5], y, fmaf(p[6], z, p[7])));
        const float ix = un * s;
        const float iy = vn * s;

        const float x0f = floorf(ix), y0f = floorf(iy);
        const float x1f = x0f + 1.f,  y1f = y0f + 1.f;
        const float wx1 = ix - x0f,   wy1 = iy - y0f;
        const float wx0 = 1.f - wx1,  wy0 = 1.f - wy1;

        const bool bx0 = zok & (x0f >= 0.f) & (x0f <= 95.f);
        const bool bx1 = zok & (x1f >= 0.f) & (x1f <= 95.f);
        const bool by0 = (y0f >= 0.f) & (y0f <= 95.f);
        const bool by1 = (y1f >= 0.f) & (y1f <= 95.f);

        unsigned pk[4];
        #define VT_SETUP(J, BX, BY, XF, YF, WX, WY)                           \
            {                                                                 \
                const bool v = (BX) & (BY);                                   \
                const unsigned raw = (unsigned)(int)fmaf((YF), 96.f, (XF)) * 4u; \
                const float wc = v ? (WX) * (WY) : 0.f;                       \
                const __half hw = __float2half_rn(wc);                        \
                const unsigned whb = (unsigned)*(const unsigned short*)&hw;   \
                pk[J] = (v ? raw : 0u) | (whb << 16);                         \
            }
        VT_SETUP(0, bx0, by0, x0f, y0f, wx0, wy0)
        VT_SETUP(1, bx1, by0, x1f, y0f, wx1, wy0)
        VT_SETUP(2, bx0, by1, x0f, y1f, wx0, wy1)
        VT_SETUP(3, bx1, by1, x1f, y1f, wx1, wy1)
        #undef VT_SETUP

        sPack[tid] = make_uint4(pk[0], pk[1], pk[2], pk[3]);
    }
    __syncthreads();

    // ---------------- Phase 2: wide fp16 gather (4 threads per voxel) ------
    const int g    = tid & 3;          // channel octet (8 halves = 16B)
    const int vloc = tid >> 2;         // voxel within block

    float acc0 = 0.f, acc1 = 0.f, acc2 = 0.f, acc3 = 0.f;
    float acc4 = 0.f, acc5 = 0.f, acc6 = 0.f, acc7 = 0.f;

    // rows are 32 halves = 4 uint4; thread g takes uint4 #g
    const uint4* hb = (const uint4*)g_hmT + b * C_ * (HWK / 8) + g;

    #pragma unroll
    for (int c = 0; c < C_; c++) {
        const uint4* cb = hb + c * (HWK / 8);
        const uint4 q = sPack[vloc * 4 + c];

        if ((q.x | q.y | q.z | q.w) & 0xFFFF0000u) {
            __half2 cam0 = u2h(0u), cam1 = u2h(0u);
            __half2 cam2 = u2h(0u), cam3 = u2h(0u);

            #define VT_CORNER(Q)                                              \
                if ((Q) >> 16) {                                              \
                    const uint4 v = cb[(Q) & 0xFFFFu];                        \
                    const __half2 w2 = u2h(__byte_perm((Q), (Q), 0x3232));    \
                    cam0 = __hfma2(w2, u2h(v.x), cam0);                       \
                    cam1 = __hfma2(w2, u2h(v.y), cam1);                       \
                    cam2 = __hfma2(w2, u2h(v.z), cam2);                       \
                    cam3 = __hfma2(w2, u2h(v.w), cam3);                       \
                }
            VT_CORNER(q.x)
            VT_CORNER(q.y)
            VT_CORNER(q.z)
            VT_CORNER(q.w)
            #undef VT_CORNER

            float2 f;
            f = __half22float2(cam0); acc0 += f.x; acc1 += f.y;
            f = __half22float2(cam1); acc2 += f.x; acc3 += f.y;
            f = __half22float2(cam2); acc4 += f.x; acc5 += f.y;
            f = __half22float2(cam3); acc6 += f.x; acc7 += f.y;
        }
    }

    // stage into smem for coalesced writeout (conflict-free: bank = vloc + 8g)
    {
        float* t = &tile[vloc][8 * g];
        t[0] = acc0; t[1] = acc1; t[2] = acc2; t[3] = acc3;
        t[4] = acc4; t[5] = acc5; t[6] = acc6; t[7] = acc7;
    }
    __syncthreads();

    const int i  = tid & 31;   // voxel within block
    const int kb = tid >> 5;   // 0..3
    #pragma unroll
    for (int r = 0; r < 8; r++) {
        const int k = r * 4 + kb;
        out[(b * K_ + k) * NV + nb + i] = tile[i][k];
    }
}

// ---------------------------------------------------------------------------
// Launch
// ---------------------------------------------------------------------------
extern "C" void kernel_launch(void* const* d_in, const int* in_sizes, int n_in,
                              void* d_out, int out_size) {
    const float* heatmaps = (const float*)d_in[0];  // (B,C,K,H,W)
    const float* P        = (const float*)d_in[1];  // (B,C,3,4)
    const float* coords   = (const float*)d_in[2];  // (B,D,D,D,3)
    const float* conf     = (const float*)d_in[3];  // (B,C,K)
    float* out            = (float*)d_out;          // (B,K,D,D,D)

    dim3 tgrid(W_ / 32, H_ / 8, B_ * C_);
    dim3 tblk(32, 32);
    vt_transpose_kernel<<<tgrid, tblk>>>(heatmaps, conf);

    const int nblocks = (B_ * NV) / 32;   // 32 voxels per block
    vt_unproject_kernel<<<nblocks, 128>>>(P, coords, out);
}

// round 9
// speedup vs baseline: 1.8962x; 1.0251x over previous
#include <cuda_runtime.h>
#include <cuda_fp16.h>

// Problem constants (fixed by the reference)
#define B_  2
#define C_  4
#define K_  32
#define H_  96
#define W_  96
#define D_  64
#define NV  (D_*D_*D_)          // 262144 voxels per batch
#define HWK (H_*W_*K_)

// Transposed, confidence-scaled heatmaps in fp16: [b,c,h,w,k] (4.7 MB)
__device__ __half g_hmT[B_ * C_ * HWK];

__device__ __forceinline__ float frcp_approx(float x) {
    float r; asm("rcp.approx.f32 %0, %1;" : "=f"(r) : "f"(x)); return r;
}
__device__ __forceinline__ __half2 u2h(unsigned v) {
    __half2 h; *(unsigned*)&h = v; return h;
}

// ---------------------------------------------------------------------------
// Kernel 1: transpose (B,C,K,H,W) -> fp16 (B,C,H,W,K), folding normalized conf.
// grid (W/32, H/8, B*C), block (32,32). Stages 8 h-rows, single barrier,
// coalesced half2 stores.
// ---------------------------------------------------------------------------
__global__ void vt_transpose_kernel(const float* __restrict__ hm,
                                    const float* __restrict__ conf) {
    __shared__ float tile[8][32][33];
    __shared__ float sCn[32];
    const int bc = blockIdx.z;            // b*C + c
    const int b  = bc >> 2;
    const int w0 = blockIdx.x * 32;
    const int h0 = blockIdx.y * 8;
    const int tx = threadIdx.x, ty = threadIdx.y;
    const int tid = ty * 32 + tx;

    if (ty == 0) {
        const int k = tx;
        float s = 0.f;
        #pragma unroll
        for (int cc = 0; cc < C_; cc++) s += conf[(b * C_ + cc) * K_ + k];
        sCn[k] = conf[bc * K_ + k] / s;
    }
    __syncthreads();

    const float cn = sCn[ty];             // k = ty on the read side
    #pragma unroll
    for (int hh = 0; hh < 8; hh++)
        tile[hh][ty][tx] =
            hm[((bc * K_ + ty) * H_ + h0 + hh) * W_ + w0 + tx] * cn;
    __syncthreads();

    __half2* outT = (__half2*)g_hmT;
    #pragma unroll
    for (int i = 0; i < 4; i++) {
        const int idx = tid + i * 1024;
        const int h       = idx >> 9;         // 0..7
        const int w_local = (idx >> 4) & 31;  // 0..31
        const int k2      = idx & 15;         // half2 index 0..15
        outT[(((bc * H_ + h0 + h) * W_ + w0 + w_local) * K_) / 2 + k2] =
            __floats2half2_rn(tile[h][2 * k2 + 0][w_local],
                              tile[h][2 * k2 + 1][w_local]);
    }
}

// ---------------------------------------------------------------------------
// Kernel 2: two-phase unprojection. Block = 128 threads = 32 voxels.
// Phase 1: every thread computes setup for one (voxel, cam) pair; each corner
//          packed into one uint: low16 = row index*4 (uint4 units),
//          high16 = fp16 weight bits (0 if invalid).
// Phase 2: 4 threads/voxel (8 channels each, uint4 = 8 fp16). Bilinear AND
//          camera-pair combine in HFMA2; fp32 convert+add twice per voxel.
// ---------------------------------------------------------------------------
__global__ __launch_bounds__(128, 12) void vt_unproject_kernel(
    const float* __restrict__ P,       // (B,C,3,4)
    const float* __restrict__ coords,  // (B,D,D,D,3)
    float* __restrict__ out)           // (B,K,D,D,D)
{
    const int tid = threadIdx.x;
    const int b   = blockIdx.x >> 13;            // NV/32 = 8192 blocks/batch
    const int nb  = (blockIdx.x & 8191) * 32;    // base voxel within batch

    __shared__ float sP[C_ * 12];
    __shared__ float sCrd[32 * 3];
    __shared__ uint4 sPack[128];       // packed (idx*4 | wh<<16) per corner
    __shared__ float tile[32][33];

    if (tid < C_ * 12) sP[tid] = P[b * C_ * 12 + tid];
    if (tid < 96)      sCrd[tid] = coords[(b * NV + nb) * 3 + tid];
    __syncthreads();

    // ---------------- Phase 1: setup (one (voxel, cam) pair per thread) ----
    {
        const int vox = tid >> 2, cam = tid & 3;
        const float x = sCrd[vox * 3 + 0];
        const float y = sCrd[vox * 3 + 1];
        const float z = sCrd[vox * 3 + 2];
        const float* p = &sP[cam * 12];

        const float pz = fmaf(p[8], x, fmaf(p[9], y, fmaf(p[10], z, p[11])));
        const bool zok = (pz > 0.f);

        const float s  = frcp_approx(pz) * (95.0f / 96.0f);
        const float un = fmaf(p[0], x, fmaf(p[1], y, fmaf(p[2], z, p[3])));
        const float vn = fmaf(p[4], x, fmaf(p[5], y, fmaf(p[6], z, p[7])));
        const float ix = un * s;
        const float iy = vn * s;

        const float x0f = floorf(ix), y0f = floorf(iy);
        const float x1f = x0f + 1.f,  y1f = y0f + 1.f;
        const float wx1 = ix - x0f,   wy1 = iy - y0f;
        const float wx0 = 1.f - wx1,  wy0 = 1.f - wy1;

        const bool bx0 = zok & (x0f >= 0.f) & (x0f <= 95.f);
        const bool bx1 = zok & (x1f >= 0.f) & (x1f <= 95.f);
        const bool by0 = (y0f >= 0.f) & (y0f <= 95.f);
        const bool by1 = (y1f >= 0.f) & (y1f <= 95.f);

        unsigned pk[4];
        #define VT_SETUP(J, BX, BY, XF, YF, WX, WY)                           \
            {                                                                 \
                const bool v = (BX) & (BY);                                   \
                const unsigned raw = (unsigned)(int)fmaf((YF), 96.f, (XF)) * 4u; \
                const float wc = v ? (WX) * (WY) : 0.f;                       \
                const __half hw = __float2half_rn(wc);                        \
                const unsigned whb = (unsigned)*(const unsigned short*)&hw;   \
                pk[J] = (v ? raw : 0u) | (whb << 16);                         \
            }
        VT_SETUP(0, bx0, by0, x0f, y0f, wx0, wy0)
        VT_SETUP(1, bx1, by0, x1f, y0f, wx1, wy0)
        VT_SETUP(2, bx0, by1, x0f, y1f, wx0, wy1)
        VT_SETUP(3, bx1, by1, x1f, y1f, wx1, wy1)
        #undef VT_SETUP

        sPack[tid] = make_uint4(pk[0], pk[1], pk[2], pk[3]);
    }
    __syncthreads();

    // ---------------- Phase 2: wide fp16 gather (4 threads per voxel) ------
    const int g    = tid & 3;          // channel octet (8 halves = 16B)
    const int vloc = tid >> 2;         // voxel within block

    float acc0 = 0.f, acc1 = 0.f, acc2 = 0.f, acc3 = 0.f;
    float acc4 = 0.f, acc5 = 0.f, acc6 = 0.f, acc7 = 0.f;

    // rows are 32 halves = 4 uint4; thread g takes uint4 #g
    const uint4* hb = (const uint4*)g_hmT + b * C_ * (HWK / 8) + g;

    #pragma unroll
    for (int cp = 0; cp < 2; cp++) {   // camera pairs {0,1}, {2,3}
        __half2 cam0 = u2h(0u), cam1 = u2h(0u);
        __half2 cam2 = u2h(0u), cam3 = u2h(0u);

        #pragma unroll
        for (int cc = 0; cc < 2; cc++) {
            const int c = cp * 2 + cc;
            const uint4* cb = hb + c * (HWK / 8);
            const uint4 q = sPack[vloc * 4 + c];

            if ((q.x | q.y | q.z | q.w) > 0xFFFFu) {
                #define VT_CORNER(Q)                                          \
                    if ((Q) > 0xFFFFu) {                                      \
                        const uint4 v = cb[(Q) & 0xFFFFu];                    \
                        const __half2 w2 = u2h(__byte_perm((Q), (Q), 0x3232)); \
                        cam0 = __hfma2(w2, u2h(v.x), cam0);                   \
                        cam1 = __hfma2(w2, u2h(v.y), cam1);                   \
                        cam2 = __hfma2(w2, u2h(v.z), cam2);                   \
                        cam3 = __hfma2(w2, u2h(v.w), cam3);                   \
                    }
                VT_CORNER(q.x)
                VT_CORNER(q.y)
                VT_CORNER(q.z)
                VT_CORNER(q.w)
                #undef VT_CORNER
            }
        }

        float2 f;
        f = __half22float2(cam0); acc0 += f.x; acc1 += f.y;
        f = __half22float2(cam1); acc2 += f.x; acc3 += f.y;
        f = __half22float2(cam2); acc4 += f.x; acc5 += f.y;
        f = __half22float2(cam3); acc6 += f.x; acc7 += f.y;
    }

    // stage into smem (stride-33 scalar stores: conflict-free)
    {
        float* t = &tile[vloc][8 * g];
        t[0] = acc0; t[1] = acc1; t[2] = acc2; t[3] = acc3;
        t[4] = acc4; t[5] = acc5; t[6] = acc6; t[7] = acc7;
    }
    __syncthreads();

    // vectorized writeout: 2 float4 per thread (k, 4-voxel group)
    #pragma unroll
    for (int s = 0; s < 2; s++) {
        const int idx = tid + s * 128;    // 0..255
        const int k = idx >> 3;           // 0..31
        const int a = idx & 7;            // group of 4 voxels
        float4 vv;
        vv.x = tile[4 * a + 0][k];
        vv.y = tile[4 * a + 1][k];
        vv.z = tile[4 * a + 2][k];
        vv.w = tile[4 * a + 3][k];
        *(float4*)&out[(b * K_ + k) * NV + nb + 4 * a] = vv;
    }
}

// ---------------------------------------------------------------------------
// Launch
// ---------------------------------------------------------------------------
extern "C" void kernel_launch(void* const* d_in, const int* in_sizes, int n_in,
                              void* d_out, int out_size) {
    const float* heatmaps = (const float*)d_in[0];  // (B,C,K,H,W)
    const float* P        = (const float*)d_in[1];  // (B,C,3,4)
    const float* coords   = (const float*)d_in[2];  // (B,D,D,D,3)
    const float* conf     = (const float*)d_in[3];  // (B,C,K)
    float* out            = (float*)d_out;          // (B,K,D,D,D)

    dim3 tgrid(W_ / 32, H_ / 8, B_ * C_);
    dim3 tblk(32, 32);
    vt_transpose_kernel<<<tgrid, tblk>>>(heatmaps, conf);

    const int nblocks = (B_ * NV) / 32;   // 32 voxels per block
    vt_unproject_kernel<<<nblocks, 128>>>(P, coords, out);
}